// round 7
// baseline (speedup 1.0000x reference)
#include <cuda_runtime.h>

#define I_DIM 28
#define H_DIM 64
#define T_DIM 128
#define B_DIM 4096
#define OUT_DIM 10
#define TI (T_DIM * I_DIM)          // 3584
#define ROWS 28                     // batch rows per CTA (14 pairs)
#define THREADS 512
#define NBLOCKS 147                 // one CTA per SM
#define ST 18                       // pair-row stride in u64 (144B)
#define ST_F 36
#define K0 46                       // half0: Whh rows [0,46); half1: [46,64)

typedef unsigned long long u64;

__device__ __forceinline__ u64 pack2(float lo, float hi) {
    u64 r; asm("mov.b64 %0, {%1, %2};" : "=l"(r) : "f"(lo), "f"(hi)); return r;
}
__device__ __forceinline__ void unpack2(u64 v, float& lo, float& hi) {
    asm("mov.b64 {%0, %1}, %2;" : "=f"(lo), "=f"(hi) : "l"(v));
}
__device__ __forceinline__ u64 ffma2(u64 a, u64 b, u64 c) {
    u64 d; asm("fma.rn.f32x2 %0, %1, %2, %3;" : "=l"(d) : "l"(a), "l"(b), "l"(c)); return d;
}
__device__ __forceinline__ u64 fadd2(u64 a, u64 b) {
    u64 d; asm("add.rn.f32x2 %0, %1, %2;" : "=l"(d) : "l"(a), "l"(b)); return d;
}
// ---- PROVEN activations (end-to-end rel_err 2.9e-7; tanh.approx is NOT safe here) ----
__device__ __forceinline__ float rcpa(float x) { float r; asm("rcp.approx.f32 %0, %1;" : "=f"(r) : "f"(x)); return r; }
__device__ __forceinline__ float ex2a(float x) { float r; asm("ex2.approx.f32 %0, %1;" : "=f"(r) : "f"(x)); return r; }
__device__ __forceinline__ float sigm(float x)  { return rcpa(1.0f + ex2a(-1.4426950408889634f * x)); }
__device__ __forceinline__ float tanh_(float x) { return fmaf(2.0f, rcpa(1.0f + ex2a(-2.8853900817779268f * x)), -1.0f); }

// smem (bytes):
//   sWhh 64*64 float4 = 65536   [k][u] -> {wi,wf,wg,wo}
//   sWih 28*64 float4 = 28672
//   sb   64    float4 = 1024
//   shT  2 x 64*18 u64 = 18432
//   sxT  2 x 28*18 u64 = 8064
//   xchg 16 slots x 256 u64 = 32768   ([slot][u][4 gates], coalesced LDS/STS.128)
#define SMEM_BYTES (65536 + 28672 + 1024 + 18432 + 8064 + 32768)   // 154496

// accumulate rows [R0,R1)
template<int R0, int R1, int NP, int PB>
__device__ __forceinline__ void accum(const float4* __restrict__ Wm,
                                      const u64* __restrict__ vbuf,
                                      int u, u64* a0, u64* a1, u64* a2, u64* a3)
{
    #pragma unroll 4
    for (int r = R0; r < R1; ++r) {
        float4 w = Wm[(r << 6) + u];
        u64 wi = pack2(w.x, w.x), wf = pack2(w.y, w.y);
        u64 wg = pack2(w.z, w.z), wo = pack2(w.w, w.w);
        const u64* vr = vbuf + r * ST;
        u64 v[NP];
        if constexpr (NP == 4) {
            ulonglong2 p0 = *(const ulonglong2*)(vr + PB);
            ulonglong2 p1 = *(const ulonglong2*)(vr + PB + 2);
            v[0] = p0.x; v[1] = p0.y; v[2] = p1.x; v[3] = p1.y;
        } else if constexpr (PB == 8) {
            ulonglong2 p0 = *(const ulonglong2*)(vr + 8);
            v[0] = p0.x; v[1] = p0.y; v[2] = vr[10];
        } else {  // PB == 11
            v[0] = vr[11];
            ulonglong2 p1 = *(const ulonglong2*)(vr + 12);
            v[1] = p1.x; v[2] = p1.y;
        }
        #pragma unroll
        for (int j = 0; j < NP; ++j) {
            a0[j] = ffma2(wi, v[j], a0[j]);
            a1[j] = ffma2(wf, v[j], a1[j]);
            a2[j] = ffma2(wg, v[j], a2[j]);
            a3[j] = ffma2(wo, v[j], a3[j]);
        }
    }
}

template<int NP, int PB>
__device__ __forceinline__ void store_h(u64* __restrict__ hrow, const u64* hn)
{
    if constexpr (NP == 4) {
        *(ulonglong2*)(hrow + PB)     = make_ulonglong2(hn[0], hn[1]);
        *(ulonglong2*)(hrow + PB + 2) = make_ulonglong2(hn[2], hn[3]);
    } else if constexpr (PB == 8) {
        *(ulonglong2*)(hrow + 8) = make_ulonglong2(hn[0], hn[1]);
        hrow[10] = hn[2];
    } else {
        hrow[11] = hn[0];
        *(ulonglong2*)(hrow + 12) = make_ulonglong2(hn[1], hn[2]);
    }
}

// HALF 0: Whh[0,K0) + combine + epilogue.  HALF 1: x-proj + Whh[K0,64) + xchg write.
template<int HALF, int NP, int PB>
__device__ __forceinline__ void mainloop(
    const float4* __restrict__ sWih, const float4* __restrict__ sWhh,
    u64* __restrict__ shT, u64* __restrict__ sxT, u64* __restrict__ xchg,
    int u, u64 bi, u64 bf, u64 bg, u64 bo,
    const float* xp0, const float* xp1, bool gv0, bool gv1, bool ev1,
    int st0, int st1)
{
    u64 a0[NP], a1[NP], a2[NP], a3[NP];
    float cc[2 * NP];
    if constexpr (HALF == 0) {
        #pragma unroll
        for (int j = 0; j < 2 * NP; ++j) cc[j] = 0.0f;
    } else {
        // carried partial for t=0: bias + Wih * x(0)  (x(0) staged in buffer 0)
        #pragma unroll
        for (int j = 0; j < NP; ++j) { a0[j] = bi; a1[j] = bf; a2[j] = bg; a3[j] = bo; }
        accum<0, I_DIM, NP, PB>(sWih, sxT, u, a0, a1, a2, a3);
    }

    for (int t = 0; t < T_DIM; ++t) {
        const bool pf = (t + 2 < T_DIM);
        float xr0 = 0.0f, xr1 = 0.0f;
        if (pf) {            // gmem prefetch of x(t+2), hidden under FMAs
            if (gv0) xr0 = xp0[(t + 2) * I_DIM];
            if (gv1) xr1 = xp1[(t + 2) * I_DIM];
        }

        const u64* hcur = shT + (t & 1) * (H_DIM * ST);
        if constexpr (HALF == 0) {
            #pragma unroll
            for (int j = 0; j < NP; ++j) { a0[j] = 0; a1[j] = 0; a2[j] = 0; a3[j] = 0; }
            accum<0, K0, NP, PB>(sWhh, hcur, u, a0, a1, a2, a3);
        } else {
            accum<K0, H_DIM, NP, PB>(sWhh, hcur, u, a0, a1, a2, a3);
            #pragma unroll
            for (int s = 0; s < NP; ++s) {
                u64* dst = xchg + ((PB + s) << 8) + (u << 2);
                *(ulonglong2*)dst       = make_ulonglong2(a0[s], a1[s]);
                *(ulonglong2*)(dst + 2) = make_ulonglong2(a2[s], a3[s]);
            }
        }
        __syncthreads();   // barrier 1: xchg visible

        if constexpr (HALF == 0) {
            #pragma unroll
            for (int s = 0; s < NP; ++s) {
                const u64* src = xchg + ((PB + s) << 8) + (u << 2);
                ulonglong2 p0 = *(const ulonglong2*)src;
                ulonglong2 p1 = *(const ulonglong2*)(src + 2);
                a0[s] = fadd2(a0[s], p0.x); a1[s] = fadd2(a1[s], p0.y);
                a2[s] = fadd2(a2[s], p1.x); a3[s] = fadd2(a3[s], p1.y);
            }
            u64 hn[NP];
            #pragma unroll
            for (int j = 0; j < NP; ++j) {
                float v0, v1;
                unpack2(a0[j], v0, v1); float i0 = sigm(v0),  i1 = sigm(v1);
                unpack2(a1[j], v0, v1); float f0 = sigm(v0),  f1 = sigm(v1);
                unpack2(a2[j], v0, v1); float g0 = tanh_(v0), g1 = tanh_(v1);
                unpack2(a3[j], v0, v1); float o0 = sigm(v0),  o1 = sigm(v1);
                float c0 = fmaf(f0, cc[2 * j],     i0 * g0);
                float c1 = fmaf(f1, cc[2 * j + 1], i1 * g1);
                cc[2 * j] = c0; cc[2 * j + 1] = c1;
                hn[j] = pack2(o0 * tanh_(c0), o1 * tanh_(c1));
            }
            store_h<NP, PB>(shT + ((t + 1) & 1) * (H_DIM * ST) + u * ST, hn);
        } else if (t + 1 < T_DIM) {
            // rebuild carried partial: bias + Wih * x(t+1); overlaps half0's MUFU epilogue
            #pragma unroll
            for (int j = 0; j < NP; ++j) { a0[j] = bi; a1[j] = bf; a2[j] = bg; a3[j] = bo; }
            accum<0, I_DIM, NP, PB>(sWih, sxT + ((t + 1) & 1) * (I_DIM * ST), u, a0, a1, a2, a3);
        }

        if (pf) {   // stage x(t+2) into buffer t&1 (not read this or next phase)
            float* xd = (float*)(sxT + (t & 1) * (I_DIM * ST));
            xd[st0] = xr0;
            if (ev1) xd[st1] = xr1;
        }
        __syncthreads();   // barrier 2: h(t+1) + staged x visible
    }
}

__global__ void __launch_bounds__(THREADS, 1)
lstm_kernel(const float* __restrict__ x,
            const float* __restrict__ W_ih,
            const float* __restrict__ W_hh,
            const float* __restrict__ b_ih,
            const float* __restrict__ b_hh,
            const float* __restrict__ W_out,
            const float* __restrict__ b_out,
            float* __restrict__ out)
{
    extern __shared__ float smem_f[];
    float4* sWhh = (float4*)smem_f;
    float4* sWih = sWhh + H_DIM * H_DIM;
    float4* sb   = sWih + I_DIM * H_DIM;
    u64*    shT  = (u64*)(sb + H_DIM);        // 2 x [k][ST]
    u64*    sxT  = shT + 2 * H_DIM * ST;      // 2 x [i][ST]
    u64*    xchg = sxT + 2 * I_DIM * ST;      // [slot][u][4]

    const int tid  = threadIdx.x;
    const int lane = tid & 31;
    const int w    = tid >> 5;
    const int s4   = w & 3;                   // SMSP
    const int j4   = w >> 2;
    // per-SMSP balanced assignment: halves {0,0,1,1}, NP {4,3,4,3}
    const int qoff[4] = {0, 2, 1, 3};
    const int q    = (s4 + qoff[j4]) & 3;     // pair-group
    const int half = j4 >> 1;
    const int u    = ((j4 & 1) << 5) | lane;  // hidden unit
    const int row0 = blockIdx.x * ROWS;

    // ---- weight staging (gate-interleaved float4, [row][u]) ----
    for (int idx = tid; idx < I_DIM * H_DIM; idx += THREADS) {
        int uu = idx & 63, ii = idx >> 6;
        sWih[ii * H_DIM + uu] = make_float4(
            W_ih[uu * I_DIM + ii],
            W_ih[(64 + uu) * I_DIM + ii],
            W_ih[(128 + uu) * I_DIM + ii],
            W_ih[(192 + uu) * I_DIM + ii]);
    }
    for (int idx = tid; idx < H_DIM * H_DIM; idx += THREADS) {
        int uu = idx & 63, kk = idx >> 6;
        sWhh[kk * H_DIM + uu] = make_float4(
            W_hh[uu * H_DIM + kk],
            W_hh[(64 + uu) * H_DIM + kk],
            W_hh[(128 + uu) * H_DIM + kk],
            W_hh[(192 + uu) * H_DIM + kk]);
    }
    if (tid < H_DIM) {
        sb[tid] = make_float4(b_ih[tid] + b_hh[tid],
                              b_ih[64 + tid] + b_hh[64 + tid],
                              b_ih[128 + tid] + b_hh[128 + tid],
                              b_ih[192 + tid] + b_hh[192 + tid]);
    }
    for (int idx = tid; idx < H_DIM * ST; idx += THREADS) shT[idx] = 0ull;  // h(0)=0

    // ---- per-thread x assignments (784 = 28*28; 2 elems/thread) ----
    int e0 = tid, e1 = tid + THREADS;
    bool ev1 = (e1 < ROWS * I_DIM);                  // e0 always valid (tid < 512 < 784)
    int er0 = e0 / I_DIM, ei0 = e0 - er0 * I_DIM;
    int ec1 = ev1 ? e1 : 0;
    int er1 = ec1 / I_DIM, ei1 = ec1 - er1 * I_DIM;
    bool gv0 = (row0 + er0 < B_DIM);
    bool gv1 = ev1 && (row0 + er1 < B_DIM);
    const float* xp0 = x + (size_t)(gv0 ? (row0 + er0) : 0) * TI + ei0;
    const float* xp1 = x + (size_t)(gv1 ? (row0 + er1) : 0) * TI + ei1;
    int st0 = ei0 * ST_F + er0;
    int st1 = ei1 * ST_F + er1;

    // stage x(0) -> buffer 0, x(1) -> buffer 1
    {
        float* x0 = (float*)sxT;
        float* x1 = (float*)(sxT + I_DIM * ST);
        x0[st0] = gv0 ? xp0[0] : 0.0f;
        x1[st0] = gv0 ? xp0[I_DIM] : 0.0f;
        if (ev1) {
            x0[st1] = gv1 ? xp1[0] : 0.0f;
            x1[st1] = gv1 ? xp1[I_DIM] : 0.0f;
        }
    }

    __syncthreads();   // weights + biases + h0 + x0/x1 visible
    float4 bv = sb[u];
    u64 bi = pack2(bv.x, bv.x), bf = pack2(bv.y, bv.y);
    u64 bg = pack2(bv.z, bv.z), bo = pack2(bv.w, bv.w);

    // pair-slot split: q0 [0,4) q1 [4,8) q2 [8,11) q3 [11,14)
    const int code = (half << 2) | q;
    switch (code) {
        case 0: mainloop<0, 4, 0 >(sWih, sWhh, shT, sxT, xchg, u, bi, bf, bg, bo, xp0, xp1, gv0, gv1, ev1, st0, st1); break;
        case 1: mainloop<0, 4, 4 >(sWih, sWhh, shT, sxT, xchg, u, bi, bf, bg, bo, xp0, xp1, gv0, gv1, ev1, st0, st1); break;
        case 2: mainloop<0, 3, 8 >(sWih, sWhh, shT, sxT, xchg, u, bi, bf, bg, bo, xp0, xp1, gv0, gv1, ev1, st0, st1); break;
        case 3: mainloop<0, 3, 11>(sWih, sWhh, shT, sxT, xchg, u, bi, bf, bg, bo, xp0, xp1, gv0, gv1, ev1, st0, st1); break;
        case 4: mainloop<1, 4, 0 >(sWih, sWhh, shT, sxT, xchg, u, bi, bf, bg, bo, xp0, xp1, gv0, gv1, ev1, st0, st1); break;
        case 5: mainloop<1, 4, 4 >(sWih, sWhh, shT, sxT, xchg, u, bi, bf, bg, bo, xp0, xp1, gv0, gv1, ev1, st0, st1); break;
        case 6: mainloop<1, 3, 8 >(sWih, sWhh, shT, sxT, xchg, u, bi, bf, bg, bo, xp0, xp1, gv0, gv1, ev1, st0, st1); break;
        default: mainloop<1, 3, 11>(sWih, sWhh, shT, sxT, xchg, u, bi, bf, bg, bo, xp0, xp1, gv0, gv1, ev1, st0, st1); break;
    }

    // ---- output head: T=128 even -> final h in buffer 0; h[k][r] at float k*ST_F + r ----
    const float* hf = (const float*)shT;
    for (int e = tid; e < ROWS * OUT_DIM; e += THREADS) {
        int r = e / OUT_DIM, o = e - r * OUT_DIM;
        if (row0 + r < B_DIM) {
            float a = b_out[o];
            #pragma unroll
            for (int k = 0; k < H_DIM; ++k)
                a = fmaf(hf[k * ST_F + r], W_out[o * H_DIM + k], a);
            out[(size_t)(row0 + r) * OUT_DIM + o] = a;
        }
    }
}

extern "C" void kernel_launch(void* const* d_in, const int* in_sizes, int n_in,
                              void* d_out, int out_size) {
    const float* x     = (const float*)d_in[0];
    const float* W_ih  = (const float*)d_in[1];
    const float* W_hh  = (const float*)d_in[2];
    const float* b_ih  = (const float*)d_in[3];
    const float* b_hh  = (const float*)d_in[4];
    const float* W_out = (const float*)d_in[5];
    const float* b_out = (const float*)d_in[6];
    float* out = (float*)d_out;

    cudaFuncSetAttribute(lstm_kernel, cudaFuncAttributeMaxDynamicSharedMemorySize, SMEM_BYTES);
    lstm_kernel<<<NBLOCKS, THREADS, SMEM_BYTES>>>(x, W_ih, W_hh, b_ih, b_hh, W_out, b_out, out);
}